// round 7
// baseline (speedup 1.0000x reference)
#include <cuda_runtime.h>
#include <cstdint>

// ---------------------------------------------------------------------------
// Problem shape (fixed by reference):
//   x: (32, 256, 64, 64) f32   v: (2, 64, 64)   W: (2, 256, 256)   T: (2, 64, 64)
//   out = invWHT( sum_p soft( v_p * (W_p @ WHT(x)), T_p ) ) / 4096 + x
// ---------------------------------------------------------------------------

#define BATCH 32
#define CH    256
#define HDIM  64
#define HW    4096                 // 64*64
#define NIMG  (BATCH * CH)         // 8192 images of 64x64

// Scratch (device globals: allowed; no runtime allocation)
__device__ float g_f2[(size_t)BATCH * CH * HW];   // 128 MB: WHT(x), tf32-rounded
__device__ float g_f6[(size_t)BATCH * CH * HW];   // 128 MB: pod-summed soft-thresholded
__device__ float g_Wt[2 * 256 * 256];             // tf32-rounded weights

__device__ __forceinline__ float tf32_round(float v) {
    uint32_t u;
    asm("cvt.rna.tf32.f32 %0, %1;" : "=r"(u) : "f"(v));
    return __uint_as_float(u);
}

__device__ __forceinline__ float softthr(float s, float t) {
    float m = fmaxf(fabsf(s) - t, 0.0f);
    return copysignf(m, s);
}

// ---------------------------------------------------------------------------
// Kernel 0: round W to tf32 once
// ---------------------------------------------------------------------------
__global__ void k_convert_w(const float* __restrict__ W) {
    int i = blockIdx.x * blockDim.x + threadIdx.x;
    if (i < 2 * 256 * 256) g_Wt[i] = tf32_round(W[i]);
}

// ---------------------------------------------------------------------------
// Kernel 1: forward 2D FWHT per 64x64 image  (x -> g_f2, tf32-rounded)
// One block per image, 256 threads, smem butterflies.
// ---------------------------------------------------------------------------
__global__ __launch_bounds__(256) void k_fwht_fwd(const float* __restrict__ x) {
    __shared__ float tile[64][65];
    const size_t base = (size_t)blockIdx.x * HW;
    const int tid = threadIdx.x;

    #pragma unroll
    for (int i = 0; i < 16; i++) {
        int idx = tid + i * 256;
        tile[idx >> 6][idx & 63] = x[base + idx];
    }
    __syncthreads();

    // transform along w (inner dim)
    #pragma unroll
    for (int len = 1; len < 64; len <<= 1) {
        #pragma unroll
        for (int i = 0; i < 8; i++) {
            int p = tid + i * 256;            // 2048 disjoint pairs
            int r = p >> 5, j = p & 31;
            int ii = ((j & ~(len - 1)) << 1) | (j & (len - 1));
            float a = tile[r][ii], b = tile[r][ii + len];
            tile[r][ii] = a + b;
            tile[r][ii + len] = a - b;
        }
        __syncthreads();
    }
    // transform along h
    #pragma unroll
    for (int len = 1; len < 64; len <<= 1) {
        #pragma unroll
        for (int i = 0; i < 8; i++) {
            int p = tid + i * 256;
            int c = p & 63, j = p >> 6;
            int ii = ((j & ~(len - 1)) << 1) | (j & (len - 1));
            float a = tile[ii][c], b = tile[ii + len][c];
            tile[ii][c] = a + b;
            tile[ii + len][c] = a - b;
        }
        __syncthreads();
    }

    #pragma unroll
    for (int i = 0; i < 16; i++) {
        int idx = tid + i * 256;
        g_f2[base + idx] = tf32_round(tile[idx >> 6][idx & 63]);
    }
}

// ---------------------------------------------------------------------------
// Kernel 2: fused dual-pod GEMM + v-scale + soft-threshold + pod-sum
//   For each batch b:  g[p] = W[p](256x256) @ f2[b](256x4096)
//   f6[b,o,hw] = sum_p softthr( v[p,hw] * g[p,o,hw], T[p,hw] )
// Tile: BM=128 (o) x BN=64 (hw), K=256 in 16-wide chunks.
// 8 warps: warp_m in [0,4) x warp_n in [0,2), warp tile 32x32,
// mma.sync.m16n8k8.tf32 (2 m-tiles x 4 n-tiles per warp per pod).
// ---------------------------------------------------------------------------
#define PAD_A 20   // 16 k-cols + 4 pad  -> conflict-free a-frag loads
#define PAD_B 72   // 64 n-cols + 8 pad  -> conflict-free b-frag loads

__device__ __forceinline__ void mma_tf32(float& d0, float& d1, float& d2, float& d3,
                                         uint32_t a0, uint32_t a1, uint32_t a2, uint32_t a3,
                                         uint32_t b0, uint32_t b1) {
    asm volatile(
        "mma.sync.aligned.m16n8k8.row.col.f32.tf32.tf32.f32 "
        "{%0,%1,%2,%3}, {%4,%5,%6,%7}, {%8,%9}, {%0,%1,%2,%3};\n"
        : "+f"(d0), "+f"(d1), "+f"(d2), "+f"(d3)
        : "r"(a0), "r"(a1), "r"(a2), "r"(a3), "r"(b0), "r"(b1));
}

__global__ __launch_bounds__(256) void k_gemm_fused(const float* __restrict__ v,
                                                    const float* __restrict__ T) {
    __shared__ float sA[2][128][PAD_A];   // [pod][o-row][k]
    __shared__ float sB[16][PAD_B];       // [k][hw-col]

    const int tid  = threadIdx.x;
    const int warp = tid >> 5;
    const int lane = tid & 31;
    const int g = lane >> 2;     // group id (0..7)
    const int t = lane & 3;      // thread in group (0..3)
    const int warp_m = warp & 3; // 0..3  (32 rows each)
    const int warp_n = warp >> 2;// 0..1  (32 cols each)

    const int n0 = blockIdx.x * 64;    // hw tile
    const int m0 = blockIdx.y * 128;   // o tile
    const int b  = blockIdx.z;         // batch

    const float* f2b = g_f2 + (size_t)b * CH * HW;

    float acc[2][2][4][4];
    #pragma unroll
    for (int p = 0; p < 2; p++)
        #pragma unroll
        for (int mt = 0; mt < 2; mt++)
            #pragma unroll
            for (int nt = 0; nt < 4; nt++)
                #pragma unroll
                for (int r = 0; r < 4; r++) acc[p][mt][nt][r] = 0.0f;

    for (int kc = 0; kc < 16; kc++) {
        const int k0 = kc * 16;
        __syncthreads();
        // load B tile: 16 x 64 floats (one float4 per thread)
        {
            int kk = tid >> 4, c4 = tid & 15;
            float4 vb = *reinterpret_cast<const float4*>(&f2b[(size_t)(k0 + kk) * HW + n0 + c4 * 4]);
            *reinterpret_cast<float4*>(&sB[kk][c4 * 4]) = vb;
        }
        // load A tiles for both pods: 2 x 128 x 16 (two float4 per thread per pod)
        #pragma unroll
        for (int p = 0; p < 2; p++) {
            #pragma unroll
            for (int i = 0; i < 2; i++) {
                int idx = tid + i * 256;          // 0..511
                int r = idx >> 2, c4 = idx & 3;
                float4 va = *reinterpret_cast<const float4*>(
                    &g_Wt[p * 65536 + (m0 + r) * 256 + k0 + c4 * 4]);
                *reinterpret_cast<float4*>(&sA[p][r][c4 * 4]) = va;
            }
        }
        __syncthreads();

        #pragma unroll
        for (int kq = 0; kq < 2; kq++) {
            const int k8 = kq * 8;
            uint32_t bf[4][2];
            #pragma unroll
            for (int nt = 0; nt < 4; nt++) {
                int n = warp_n * 32 + nt * 8 + g;
                bf[nt][0] = __float_as_uint(sB[k8 + t][n]);
                bf[nt][1] = __float_as_uint(sB[k8 + t + 4][n]);
            }
            #pragma unroll
            for (int p = 0; p < 2; p++) {
                #pragma unroll
                for (int mt = 0; mt < 2; mt++) {
                    int rb = warp_m * 32 + mt * 16;
                    uint32_t a0 = __float_as_uint(sA[p][rb + g][k8 + t]);
                    uint32_t a1 = __float_as_uint(sA[p][rb + 8 + g][k8 + t]);
                    uint32_t a2 = __float_as_uint(sA[p][rb + g][k8 + t + 4]);
                    uint32_t a3 = __float_as_uint(sA[p][rb + 8 + g][k8 + t + 4]);
                    #pragma unroll
                    for (int nt = 0; nt < 4; nt++)
                        mma_tf32(acc[p][mt][nt][0], acc[p][mt][nt][1],
                                 acc[p][mt][nt][2], acc[p][mt][nt][3],
                                 a0, a1, a2, a3, bf[nt][0], bf[nt][1]);
                }
            }
        }
    }

    // Epilogue: v-scale, soft-threshold, sum over pods, store f6
    float* f6b = g_f6 + (size_t)b * CH * HW;
    #pragma unroll
    for (int nt = 0; nt < 4; nt++) {
        int hw = n0 + warp_n * 32 + nt * 8 + 2 * t;   // even -> float2 aligned
        float v0[2], v1[2], t0[2], t1[2];
        #pragma unroll
        for (int p = 0; p < 2; p++) {
            v0[p] = v[p * HW + hw];
            v1[p] = v[p * HW + hw + 1];
            t0[p] = T[p * HW + hw];
            t1[p] = T[p * HW + hw + 1];
        }
        #pragma unroll
        for (int mt = 0; mt < 2; mt++) {
            int o0 = m0 + warp_m * 32 + mt * 16 + g;  // rows o0 and o0+8
            float2 lo = make_float2(0.f, 0.f);
            float2 hi = make_float2(0.f, 0.f);
            #pragma unroll
            for (int p = 0; p < 2; p++) {
                lo.x += softthr(v0[p] * acc[p][mt][nt][0], t0[p]);
                lo.y += softthr(v1[p] * acc[p][mt][nt][1], t1[p]);
                hi.x += softthr(v0[p] * acc[p][mt][nt][2], t0[p]);
                hi.y += softthr(v1[p] * acc[p][mt][nt][3], t1[p]);
            }
            *reinterpret_cast<float2*>(&f6b[(size_t)o0 * HW + hw]) = lo;
            *reinterpret_cast<float2*>(&f6b[(size_t)(o0 + 8) * HW + hw]) = hi;
        }
    }
}

// ---------------------------------------------------------------------------
// Kernel 3: inverse 2D FWHT (* 1/4096) + residual  (g_f6, x -> out)
// ---------------------------------------------------------------------------
__global__ __launch_bounds__(256) void k_fwht_inv(const float* __restrict__ x,
                                                  float* __restrict__ out) {
    __shared__ float tile[64][65];
    const size_t base = (size_t)blockIdx.x * HW;
    const int tid = threadIdx.x;

    #pragma unroll
    for (int i = 0; i < 16; i++) {
        int idx = tid + i * 256;
        tile[idx >> 6][idx & 63] = g_f6[base + idx];
    }
    __syncthreads();

    #pragma unroll
    for (int len = 1; len < 64; len <<= 1) {
        #pragma unroll
        for (int i = 0; i < 8; i++) {
            int p = tid + i * 256;
            int r = p >> 5, j = p & 31;
            int ii = ((j & ~(len - 1)) << 1) | (j & (len - 1));
            float a = tile[r][ii], b = tile[r][ii + len];
            tile[r][ii] = a + b;
            tile[r][ii + len] = a - b;
        }
        __syncthreads();
    }
    #pragma unroll
    for (int len = 1; len < 64; len <<= 1) {
        #pragma unroll
        for (int i = 0; i < 8; i++) {
            int p = tid + i * 256;
            int c = p & 63, j = p >> 6;
            int ii = ((j & ~(len - 1)) << 1) | (j & (len - 1));
            float a = tile[ii][c], b = tile[ii + len][c];
            tile[ii][c] = a + b;
            tile[ii + len][c] = a - b;
        }
        __syncthreads();
    }

    const float inv = 1.0f / 4096.0f;
    #pragma unroll
    for (int i = 0; i < 16; i++) {
        int idx = tid + i * 256;
        out[base + idx] = fmaf(tile[idx >> 6][idx & 63], inv, x[base + idx]);
    }
}

// ---------------------------------------------------------------------------
// Launch: 4 kernels, graph-capturable (no sync, no alloc, no memcpy)
// Inputs (metadata order): x, v, W, T   -> output f32 (32*256*64*64)
// ---------------------------------------------------------------------------
extern "C" void kernel_launch(void* const* d_in, const int* in_sizes, int n_in,
                              void* d_out, int out_size) {
    const float* x = (const float*)d_in[0];
    const float* v = (const float*)d_in[1];
    const float* W = (const float*)d_in[2];
    const float* T = (const float*)d_in[3];
    float* out = (float*)d_out;

    k_convert_w<<<(2 * 256 * 256 + 255) / 256, 256>>>(W);
    k_fwht_fwd<<<NIMG, 256>>>(x);
    dim3 grid(HW / 64, CH / 128, BATCH);   // (64, 2, 32)
    k_gemm_fused<<<grid, 256>>>(v, T);
    k_fwht_inv<<<NIMG, 256>>>(x, out);
}

// round 8
// speedup vs baseline: 1.5512x; 1.5512x over previous
#include <cuda_runtime.h>
#include <cstdint>

// ---------------------------------------------------------------------------
// x: (32, 256, 64, 64) f32   v: (2, 64, 64)   W: (2, 256, 256)   T: (2, 64, 64)
// out = invWHT( sum_p soft( v_p * (W_p @ WHT(x)), T_p ) ) / 4096 + x
// ---------------------------------------------------------------------------

#define BATCH 32
#define CH    256
#define HW    4096
#define NIMG  (BATCH * CH)

__device__ float g_f2[(size_t)BATCH * CH * HW];   // WHT(x), tf32-rounded
__device__ float g_f6[(size_t)BATCH * CH * HW];   // pod-summed soft-thresholded
__device__ float g_Wt[2 * 256 * 256];             // tf32-rounded weights

__device__ __forceinline__ float tf32_round(float v) {
    uint32_t u;
    asm("cvt.rna.tf32.f32 %0, %1;" : "=r"(u) : "f"(v));
    return __uint_as_float(u);
}

__device__ __forceinline__ float softthr(float s, float t) {
    float m = fmaxf(fabsf(s) - t, 0.0f);
    return copysignf(m, s);
}

// 64-point WHT on (a[i], b[i]) pairs: lane holds elements (lane, lane+32).
// 5 shuffle stages (bits 0..4) + lane-local stage (bit 5) folded by caller.
template <int NR>
__device__ __forceinline__ void wht64_shfl(float (&a)[NR], float (&b)[NR], int lane) {
    #pragma unroll
    for (int len = 1; len <= 16; len <<= 1) {
        #pragma unroll
        for (int r = 0; r < NR; r++) {
            float pa = __shfl_xor_sync(0xffffffffu, a[r], len);
            float pb = __shfl_xor_sync(0xffffffffu, b[r], len);
            if (lane & len) { a[r] = pa - a[r]; b[r] = pb - b[r]; }
            else            { a[r] = a[r] + pa; b[r] = b[r] + pb; }
        }
    }
}

// ---------------------------------------------------------------------------
// Kernel 0: round W to tf32 once
// ---------------------------------------------------------------------------
__global__ void k_convert_w(const float* __restrict__ W) {
    int i = blockIdx.x * blockDim.x + threadIdx.x;
    if (i < 2 * 256 * 256) g_Wt[i] = tf32_round(W[i]);
}

// ---------------------------------------------------------------------------
// Kernel 1: forward 2D FWHT (x -> g_f2, tf32-rounded). Shuffle butterflies,
// one smem transpose between the two passes, coalesced gmem on both ends.
// ---------------------------------------------------------------------------
__global__ __launch_bounds__(256) void k_fwht_fwd(const float* __restrict__ x) {
    __shared__ float t[64][65];
    const size_t base = (size_t)blockIdx.x * HW;
    const int tid = threadIdx.x, lane = tid & 31, w = tid >> 5;
    float a[8], b[8];

    // pass 1: rows w*8..w*8+7 (coalesced loads)
    #pragma unroll
    for (int rr = 0; rr < 8; rr++) {
        int r = w * 8 + rr;
        a[rr] = x[base + r * 64 + lane];
        b[rr] = x[base + r * 64 + lane + 32];
    }
    wht64_shfl(a, b, lane);
    #pragma unroll
    for (int rr = 0; rr < 8; rr++) {
        float s = a[rr] + b[rr], d = a[rr] - b[rr];   // len=32 stage
        t[lane][w * 8 + rr] = s;                      // transposed store
        t[lane + 32][w * 8 + rr] = d;
    }
    __syncthreads();

    // pass 2: columns w*8..w*8+7 (rows of transposed tile, warp-private)
    #pragma unroll
    for (int rr = 0; rr < 8; rr++) {
        int c = w * 8 + rr;
        a[rr] = t[c][lane];
        b[rr] = t[c][lane + 32];
    }
    wht64_shfl(a, b, lane);
    #pragma unroll
    for (int rr = 0; rr < 8; rr++) {
        int c = w * 8 + rr;
        t[c][lane]      = a[rr] + b[rr];
        t[c][lane + 32] = a[rr] - b[rr];
    }
    __syncthreads();

    #pragma unroll
    for (int i = 0; i < 16; i++) {
        int idx = tid + i * 256;
        g_f2[base + idx] = tf32_round(t[idx & 63][idx >> 6]);
    }
}

// ---------------------------------------------------------------------------
// Kernel 2: fused dual-pod GEMM + v-scale + soft-threshold + pod-sum.
// BM=128 x BN=64, K=256 in 16-chunks, cp.async double-buffered.
// ---------------------------------------------------------------------------
#define PAD_A 20
#define PAD_B 72
#define SMEM_A_FLOATS (2 * 2 * 128 * PAD_A)          // buf, pod, row, k
#define SMEM_B_FLOATS (2 * 16 * PAD_B)               // buf, k, n
#define GEMM_SMEM_BYTES ((SMEM_A_FLOATS + SMEM_B_FLOATS) * 4)

__device__ __forceinline__ void cp_async16(void* smem, const void* gmem) {
    uint32_t s = (uint32_t)__cvta_generic_to_shared(smem);
    asm volatile("cp.async.ca.shared.global [%0], [%1], 16;\n" :: "r"(s), "l"(gmem));
}

__device__ __forceinline__ void mma_tf32(float& d0, float& d1, float& d2, float& d3,
                                         uint32_t a0, uint32_t a1, uint32_t a2, uint32_t a3,
                                         uint32_t b0, uint32_t b1) {
    asm volatile(
        "mma.sync.aligned.m16n8k8.row.col.f32.tf32.tf32.f32 "
        "{%0,%1,%2,%3}, {%4,%5,%6,%7}, {%8,%9}, {%0,%1,%2,%3};\n"
        : "+f"(d0), "+f"(d1), "+f"(d2), "+f"(d3)
        : "r"(a0), "r"(a1), "r"(a2), "r"(a3), "r"(b0), "r"(b1));
}

__global__ __launch_bounds__(256) void k_gemm_fused(const float* __restrict__ v,
                                                    const float* __restrict__ T) {
    extern __shared__ float smem[];
    float* sA = smem;                    // [(s*2+p)*128 + r]*PAD_A + k
    float* sB = smem + SMEM_A_FLOATS;    // [(s*16 + kk)]*PAD_B + n

    const int tid  = threadIdx.x;
    const int warp = tid >> 5;
    const int lane = tid & 31;
    const int g = lane >> 2;
    const int t = lane & 3;
    const int warp_m = warp & 3;
    const int warp_n = warp >> 2;

    const int n0 = blockIdx.x * 64;
    const int m0 = blockIdx.y * 128;
    const int b  = blockIdx.z;

    const float* f2b = g_f2 + (size_t)b * CH * HW;

    // prefetch helper (inlined twice)
    auto prefetch = [&](int kc, int s) {
        const int k0 = kc * 16;
        {
            int kk = tid >> 4, c4 = (tid & 15) * 4;
            cp_async16(&sB[(s * 16 + kk) * PAD_B + c4],
                       &f2b[(size_t)(k0 + kk) * HW + n0 + c4]);
        }
        #pragma unroll
        for (int p = 0; p < 2; p++) {
            #pragma unroll
            for (int i = 0; i < 2; i++) {
                int idx = tid + i * 256;
                int r = idx >> 2, c = (idx & 3) * 4;
                cp_async16(&sA[((s * 2 + p) * 128 + r) * PAD_A + c],
                           &g_Wt[p * 65536 + (m0 + r) * 256 + k0 + c]);
            }
        }
        asm volatile("cp.async.commit_group;\n");
    };

    float acc[2][2][4][4];
    #pragma unroll
    for (int p = 0; p < 2; p++)
        #pragma unroll
        for (int mt = 0; mt < 2; mt++)
            #pragma unroll
            for (int nt = 0; nt < 4; nt++)
                #pragma unroll
                for (int r = 0; r < 4; r++) acc[p][mt][nt][r] = 0.0f;

    prefetch(0, 0);

    for (int kc = 0; kc < 16; kc++) {
        const int s = kc & 1;
        if (kc + 1 < 16) prefetch(kc + 1, s ^ 1);
        else asm volatile("cp.async.commit_group;\n");   // empty group
        asm volatile("cp.async.wait_group 1;\n");
        __syncthreads();

        #pragma unroll
        for (int kq = 0; kq < 2; kq++) {
            const int k8 = kq * 8;
            uint32_t bf[4][2];
            #pragma unroll
            for (int nt = 0; nt < 4; nt++) {
                int n = warp_n * 32 + nt * 8 + g;
                bf[nt][0] = __float_as_uint(sB[(s * 16 + k8 + t) * PAD_B + n]);
                bf[nt][1] = __float_as_uint(sB[(s * 16 + k8 + t + 4) * PAD_B + n]);
            }
            #pragma unroll
            for (int p = 0; p < 2; p++) {
                #pragma unroll
                for (int mt = 0; mt < 2; mt++) {
                    int rb = warp_m * 32 + mt * 16;
                    const float* ap = &sA[((s * 2 + p) * 128) * PAD_A];
                    uint32_t a0 = __float_as_uint(ap[(rb + g) * PAD_A + k8 + t]);
                    uint32_t a1 = __float_as_uint(ap[(rb + 8 + g) * PAD_A + k8 + t]);
                    uint32_t a2 = __float_as_uint(ap[(rb + g) * PAD_A + k8 + t + 4]);
                    uint32_t a3 = __float_as_uint(ap[(rb + 8 + g) * PAD_A + k8 + t + 4]);
                    #pragma unroll
                    for (int nt = 0; nt < 4; nt++)
                        mma_tf32(acc[p][mt][nt][0], acc[p][mt][nt][1],
                                 acc[p][mt][nt][2], acc[p][mt][nt][3],
                                 a0, a1, a2, a3, bf[nt][0], bf[nt][1]);
                }
            }
        }
        __syncthreads();   // guard buffers before next prefetch overwrites
    }

    // Epilogue: v-scale, soft-threshold, sum pods
    float* f6b = g_f6 + (size_t)b * CH * HW;
    #pragma unroll
    for (int nt = 0; nt < 4; nt++) {
        int hw = n0 + warp_n * 32 + nt * 8 + 2 * t;
        float v0[2], v1[2], t0[2], t1[2];
        #pragma unroll
        for (int p = 0; p < 2; p++) {
            v0[p] = v[p * HW + hw];
            v1[p] = v[p * HW + hw + 1];
            t0[p] = T[p * HW + hw];
            t1[p] = T[p * HW + hw + 1];
        }
        #pragma unroll
        for (int mt = 0; mt < 2; mt++) {
            int o0 = m0 + warp_m * 32 + mt * 16 + g;
            float2 lo = make_float2(0.f, 0.f);
            float2 hi = make_float2(0.f, 0.f);
            #pragma unroll
            for (int p = 0; p < 2; p++) {
                lo.x += softthr(v0[p] * acc[p][mt][nt][0], t0[p]);
                lo.y += softthr(v1[p] * acc[p][mt][nt][1], t1[p]);
                hi.x += softthr(v0[p] * acc[p][mt][nt][2], t0[p]);
                hi.y += softthr(v1[p] * acc[p][mt][nt][3], t1[p]);
            }
            *reinterpret_cast<float2*>(&f6b[(size_t)o0 * HW + hw]) = lo;
            *reinterpret_cast<float2*>(&f6b[(size_t)(o0 + 8) * HW + hw]) = hi;
        }
    }
}

// ---------------------------------------------------------------------------
// Kernel 3: inverse 2D FWHT (*1/4096) + residual, shuffle butterflies
// ---------------------------------------------------------------------------
__global__ __launch_bounds__(256) void k_fwht_inv(const float* __restrict__ x,
                                                  float* __restrict__ out) {
    __shared__ float t[64][65];
    const size_t base = (size_t)blockIdx.x * HW;
    const int tid = threadIdx.x, lane = tid & 31, w = tid >> 5;
    float a[8], b[8];

    #pragma unroll
    for (int rr = 0; rr < 8; rr++) {
        int r = w * 8 + rr;
        a[rr] = g_f6[base + r * 64 + lane];
        b[rr] = g_f6[base + r * 64 + lane + 32];
    }
    wht64_shfl(a, b, lane);
    #pragma unroll
    for (int rr = 0; rr < 8; rr++) {
        t[lane][w * 8 + rr]      = a[rr] + b[rr];
        t[lane + 32][w * 8 + rr] = a[rr] - b[rr];
    }
    __syncthreads();

    #pragma unroll
    for (int rr = 0; rr < 8; rr++) {
        int c = w * 8 + rr;
        a[rr] = t[c][lane];
        b[rr] = t[c][lane + 32];
    }
    wht64_shfl(a, b, lane);
    #pragma unroll
    for (int rr = 0; rr < 8; rr++) {
        int c = w * 8 + rr;
        t[c][lane]      = a[rr] + b[rr];
        t[c][lane + 32] = a[rr] - b[rr];
    }
    __syncthreads();

    const float inv = 1.0f / 4096.0f;
    #pragma unroll
    for (int i = 0; i < 16; i++) {
        int idx = tid + i * 256;
        out[base + idx] = fmaf(t[idx & 63][idx >> 6], inv, x[base + idx]);
    }
}

// ---------------------------------------------------------------------------
extern "C" void kernel_launch(void* const* d_in, const int* in_sizes, int n_in,
                              void* d_out, int out_size) {
    const float* x = (const float*)d_in[0];
    const float* v = (const float*)d_in[1];
    const float* W = (const float*)d_in[2];
    const float* T = (const float*)d_in[3];
    float* out = (float*)d_out;

    cudaFuncSetAttribute(k_gemm_fused,
                         cudaFuncAttributeMaxDynamicSharedMemorySize,
                         GEMM_SMEM_BYTES);

    k_convert_w<<<(2 * 256 * 256 + 255) / 256, 256>>>(W);
    k_fwht_fwd<<<NIMG, 256>>>(x);
    dim3 grid(HW / 64, CH / 128, BATCH);
    k_gemm_fused<<<grid, 256, GEMM_SMEM_BYTES>>>(v, T);
    k_fwht_inv<<<NIMG, 256>>>(x, out);
}

// round 9
// speedup vs baseline: 1.8544x; 1.1955x over previous
#include <cuda_runtime.h>
#include <cstdint>

// ---------------------------------------------------------------------------
// x: (32, 256, 64, 64) f32   v: (2, 64, 64)   W: (2, 256, 256)   T: (2, 64, 64)
// out = invWHT( sum_p soft( v_p * (W_p @ WHT(x)), T_p ) ) / 4096 + x
// ---------------------------------------------------------------------------

#define BATCH 32
#define CH    256
#define HW    4096
#define NIMG  (BATCH * CH)

__device__ float g_f2[(size_t)BATCH * CH * HW];   // WHT(x), tf32-rounded
__device__ float g_f6[(size_t)BATCH * CH * HW];   // pod-summed soft-thresholded
// W in tf32, pre-swizzled into mma fragment order:
//   [pod(2)][kq8(32)][mt16(16)][lane(32)][4 floats]
__device__ float g_WtF[2 * 32 * 16 * 32 * 4];

__device__ __forceinline__ float tf32_round(float v) {
    uint32_t u;
    asm("cvt.rna.tf32.f32 %0, %1;" : "=r"(u) : "f"(v));
    return __uint_as_float(u);
}

__device__ __forceinline__ float softthr(float s, float t) {
    float m = fmaxf(fabsf(s) - t, 0.0f);
    return copysignf(m, s);
}

// ---------------------------------------------------------------------------
// 64-pt WHT, data held as 8 CONSECUTIVE elements per thread (a[0..7] = elems
// 8*sub .. 8*sub+7, sub = lane & 7). Stages 1,2,4 are register-local;
// stages 8,16,32 are shfl.xor with masks 1,2,4 (within the 8-lane sub-group).
// ---------------------------------------------------------------------------
__device__ __forceinline__ void wht8_local(float (&a)[8]) {
    #pragma unroll
    for (int j = 0; j < 8; j += 2) { float s = a[j] + a[j+1], d = a[j] - a[j+1]; a[j] = s; a[j+1] = d; }
    #pragma unroll
    for (int j0 = 0; j0 < 8; j0 += 4)
        #pragma unroll
        for (int j = j0; j < j0 + 2; j++) { float s = a[j] + a[j+2], d = a[j] - a[j+2]; a[j] = s; a[j+2] = d; }
    #pragma unroll
    for (int j = 0; j < 4; j++) { float s = a[j] + a[j+4], d = a[j] - a[j+4]; a[j] = s; a[j+4] = d; }
}

__device__ __forceinline__ void wht64_vec(float (&a)[8], float (&b)[8], int lane) {
    wht8_local(a);
    wht8_local(b);
    #pragma unroll
    for (int mask = 1; mask <= 4; mask <<= 1) {
        bool hi = (lane & mask) != 0;
        #pragma unroll
        for (int i = 0; i < 8; i++) {
            float pa = __shfl_xor_sync(0xffffffffu, a[i], mask);
            float pb = __shfl_xor_sync(0xffffffffu, b[i], mask);
            a[i] = hi ? pa - a[i] : a[i] + pa;
            b[i] = hi ? pb - b[i] : b[i] + pb;
        }
    }
}

// ---------------------------------------------------------------------------
// Kernel 0: tf32-round W and scatter into mma fragment order.
// a0=W[m16+g][q8+t]  a1=W[m16+8+g][q8+t]  a2=W[m16+g][q8+t+4]  a3=W[..+8..][t+4]
// ---------------------------------------------------------------------------
__global__ void k_pack_w(const float* __restrict__ W) {
    int idx = blockIdx.x * blockDim.x + threadIdx.x;     // 32768 threads
    if (idx >= 2 * 32 * 16 * 32) return;
    int lane = idx & 31;
    int m    = (idx >> 5) & 15;
    int q    = (idx >> 9) & 31;
    int p    = idx >> 14;
    int g = lane >> 2, t = lane & 3;
    const float* Wp = W + p * 65536;
    float4 f;
    f.x = tf32_round(Wp[(m * 16 +     g) * 256 + q * 8 + t    ]);
    f.y = tf32_round(Wp[(m * 16 + 8 + g) * 256 + q * 8 + t    ]);
    f.z = tf32_round(Wp[(m * 16 +     g) * 256 + q * 8 + t + 4]);
    f.w = tf32_round(Wp[(m * 16 + 8 + g) * 256 + q * 8 + t + 4]);
    *reinterpret_cast<float4*>(&g_WtF[(size_t)idx * 4]) = f;
}

// ---------------------------------------------------------------------------
// Kernel 1: forward 2D FWHT (x -> g_f2, tf32-rounded)
// ---------------------------------------------------------------------------
__global__ __launch_bounds__(256) void k_fwht_fwd(const float* __restrict__ x) {
    __shared__ float t[64][65];
    const size_t base = (size_t)blockIdx.x * HW;
    const int tid = threadIdx.x, lane = tid & 31;
    const int sub = tid & 7;        // 8-elem chunk within the 64-vector
    const int grp = tid >> 3;       // 0..31
    float a[8], b[8];

    // row pass: rows grp and grp+32, cols 8*sub..8*sub+7
    {
        const float* r0 = &x[base + grp * 64 + sub * 8];
        const float* r1 = &x[base + (grp + 32) * 64 + sub * 8];
        *reinterpret_cast<float4*>(&a[0]) = *reinterpret_cast<const float4*>(r0);
        *reinterpret_cast<float4*>(&a[4]) = *reinterpret_cast<const float4*>(r0 + 4);
        *reinterpret_cast<float4*>(&b[0]) = *reinterpret_cast<const float4*>(r1);
        *reinterpret_cast<float4*>(&b[4]) = *reinterpret_cast<const float4*>(r1 + 4);
    }
    wht64_vec(a, b, lane);
    #pragma unroll
    for (int i = 0; i < 8; i++) {
        t[grp][sub * 8 + i]      = a[i];
        t[grp + 32][sub * 8 + i] = b[i];
    }
    __syncthreads();

    // column pass: cols grp and grp+32, rows 8*sub..8*sub+7
    #pragma unroll
    for (int i = 0; i < 8; i++) {
        a[i] = t[sub * 8 + i][grp];
        b[i] = t[sub * 8 + i][grp + 32];
    }
    wht64_vec(a, b, lane);
    __syncthreads();
    #pragma unroll
    for (int i = 0; i < 8; i++) {
        t[sub * 8 + i][grp]      = a[i];
        t[sub * 8 + i][grp + 32] = b[i];
    }
    __syncthreads();

    #pragma unroll
    for (int i = 0; i < 16; i++) {
        int idx = tid + i * 256;
        g_f2[base + idx] = tf32_round(t[idx >> 6][idx & 63]);
    }
}

// ---------------------------------------------------------------------------
// Kernel 2: fused dual-pod GEMM + v-scale + soft-threshold + pod-sum.
// BM=128 x BN=64, K=256 in 16-chunks, 3-stage cp.async, 1 sync/chunk.
// A consumed via LDS.128 from fragment-order smem; B XOR-swizzled.
// ---------------------------------------------------------------------------
#define A_STG 4096                        // floats per stage (2*2*8*32*4)
#define B_STG 1024                        // floats per stage (16*64)
#define STG   (A_STG + B_STG)             // 5120 floats
#define NSTAGE 3
#define GEMM_SMEM_BYTES (NSTAGE * STG * 4)   // 61440

__device__ __forceinline__ void cp_async16(void* smem, const void* gmem) {
    uint32_t s = (uint32_t)__cvta_generic_to_shared(smem);
    asm volatile("cp.async.ca.shared.global [%0], [%1], 16;\n" :: "r"(s), "l"(gmem));
}

__device__ __forceinline__ void mma_tf32(float& d0, float& d1, float& d2, float& d3,
                                         uint32_t a0, uint32_t a1, uint32_t a2, uint32_t a3,
                                         uint32_t b0, uint32_t b1) {
    asm volatile(
        "mma.sync.aligned.m16n8k8.row.col.f32.tf32.tf32.f32 "
        "{%0,%1,%2,%3}, {%4,%5,%6,%7}, {%8,%9}, {%0,%1,%2,%3};\n"
        : "+f"(d0), "+f"(d1), "+f"(d2), "+f"(d3)
        : "r"(a0), "r"(a1), "r"(a2), "r"(a3), "r"(b0), "r"(b1));
}

__global__ __launch_bounds__(256) void k_gemm_fused(const float* __restrict__ v,
                                                    const float* __restrict__ T) {
    extern __shared__ float smem[];

    const int tid  = threadIdx.x;
    const int warp = tid >> 5;
    const int lane = tid & 31;
    const int g = lane >> 2;
    const int t = lane & 3;
    const int warp_m = warp & 3;
    const int warp_n = warp >> 2;

    const int n0 = blockIdx.x * 64;
    const int m0 = blockIdx.y * 128;
    const int m16base = blockIdx.y * 8;
    const int b  = blockIdx.z;

    const float* f2b = g_f2 + (size_t)b * CH * HW;

    auto prefetch = [&](int kc, int st) {
        // A: 1024 16B-units in fragment-linear order
        #pragma unroll
        for (int i = 0; i < 4; i++) {
            int u  = i * 256 + tid;
            int p  = u >> 9;
            int r  = u & 511;
            int qq = r >> 8;
            int r2 = r & 255;
            int mm = r2 >> 5;
            int ln = r2 & 31;
            const float* src = &g_WtF[(size_t)((((p * 32 + kc * 2 + qq) * 16) + m16base + mm) * 32 + ln) * 4];
            cp_async16(&smem[st * STG + u * 4], src);
        }
        // B: 16 rows x 64 cols, XOR swizzle col ^= (k&3)<<3 (16B-chunk safe)
        {
            int kk = tid >> 4, c4 = (tid & 15) * 4;
            int col = c4 ^ ((kk & 3) << 3);
            cp_async16(&smem[st * STG + A_STG + kk * 64 + col],
                       &f2b[(size_t)(kc * 16 + kk) * HW + n0 + c4]);
        }
        asm volatile("cp.async.commit_group;\n");
    };

    float acc[2][2][4][4];
    #pragma unroll
    for (int p = 0; p < 2; p++)
        #pragma unroll
        for (int mt = 0; mt < 2; mt++)
            #pragma unroll
            for (int nt = 0; nt < 4; nt++)
                #pragma unroll
                for (int r = 0; r < 4; r++) acc[p][mt][nt][r] = 0.0f;

    prefetch(0, 0);
    prefetch(1, 1);

    for (int kc = 0; kc < 16; kc++) {
        const int st = kc % NSTAGE;
        __syncthreads();                         // all warps done with kc-1's buffer
        if (kc + 2 < 16) prefetch(kc + 2, (kc + 2) % NSTAGE);
        else asm volatile("cp.async.commit_group;\n");
        asm volatile("cp.async.wait_group 2;\n"); // stage kc resident
        __syncthreads();

        const float* sA = &smem[st * STG];
        const float* sB = &smem[st * STG + A_STG];

        #pragma unroll
        for (int kq = 0; kq < 2; kq++) {
            const int k8 = kq * 8;
            // B fragments (conflict-free: bank = g + 8*(nt^t))
            uint32_t bf[4][2];
            #pragma unroll
            for (int nt = 0; nt < 4; nt++) {
                int col = (warp_n * 32 + nt * 8 + g) ^ (t << 3);
                bf[nt][0] = __float_as_uint(sB[(k8 + t) * 64 + col]);
                bf[nt][1] = __float_as_uint(sB[(k8 + t + 4) * 64 + col]);
            }
            #pragma unroll
            for (int p = 0; p < 2; p++) {
                #pragma unroll
                for (int mt = 0; mt < 2; mt++) {
                    int u = p * 512 + kq * 256 + (warp_m * 2 + mt) * 32 + lane;
                    float4 af = *reinterpret_cast<const float4*>(&sA[u * 4]);
                    uint32_t a0 = __float_as_uint(af.x);
                    uint32_t a1 = __float_as_uint(af.y);
                    uint32_t a2 = __float_as_uint(af.z);
                    uint32_t a3 = __float_as_uint(af.w);
                    #pragma unroll
                    for (int nt = 0; nt < 4; nt++)
                        mma_tf32(acc[p][mt][nt][0], acc[p][mt][nt][1],
                                 acc[p][mt][nt][2], acc[p][mt][nt][3],
                                 a0, a1, a2, a3, bf[nt][0], bf[nt][1]);
                }
            }
        }
    }

    // Epilogue: v-scale, soft-threshold, sum pods
    float* f6b = g_f6 + (size_t)b * CH * HW;
    #pragma unroll
    for (int nt = 0; nt < 4; nt++) {
        int hw = n0 + warp_n * 32 + nt * 8 + 2 * t;
        float v0[2], v1[2], t0[2], t1[2];
        #pragma unroll
        for (int p = 0; p < 2; p++) {
            v0[p] = v[p * HW + hw];
            v1[p] = v[p * HW + hw + 1];
            t0[p] = T[p * HW + hw];
            t1[p] = T[p * HW + hw + 1];
        }
        #pragma unroll
        for (int mt = 0; mt < 2; mt++) {
            int o0 = m0 + warp_m * 32 + mt * 16 + g;
            float2 lo = make_float2(0.f, 0.f);
            float2 hi = make_float2(0.f, 0.f);
            #pragma unroll
            for (int p = 0; p < 2; p++) {
                lo.x += softthr(v0[p] * acc[p][mt][nt][0], t0[p]);
                lo.y += softthr(v1[p] * acc[p][mt][nt][1], t1[p]);
                hi.x += softthr(v0[p] * acc[p][mt][nt][2], t0[p]);
                hi.y += softthr(v1[p] * acc[p][mt][nt][3], t1[p]);
            }
            *reinterpret_cast<float2*>(&f6b[(size_t)o0 * HW + hw]) = lo;
            *reinterpret_cast<float2*>(&f6b[(size_t)(o0 + 8) * HW + hw]) = hi;
        }
    }
}

// ---------------------------------------------------------------------------
// Kernel 3: inverse 2D FWHT (*1/4096) + residual
// ---------------------------------------------------------------------------
__global__ __launch_bounds__(256) void k_fwht_inv(const float* __restrict__ x,
                                                  float* __restrict__ out) {
    __shared__ float t[64][65];
    const size_t base = (size_t)blockIdx.x * HW;
    const int tid = threadIdx.x, lane = tid & 31;
    const int sub = tid & 7;
    const int grp = tid >> 3;
    float a[8], b[8];

    {
        const float* r0 = &g_f6[base + grp * 64 + sub * 8];
        const float* r1 = &g_f6[base + (grp + 32) * 64 + sub * 8];
        *reinterpret_cast<float4*>(&a[0]) = *reinterpret_cast<const float4*>(r0);
        *reinterpret_cast<float4*>(&a[4]) = *reinterpret_cast<const float4*>(r0 + 4);
        *reinterpret_cast<float4*>(&b[0]) = *reinterpret_cast<const float4*>(r1);
        *reinterpret_cast<float4*>(&b[4]) = *reinterpret_cast<const float4*>(r1 + 4);
    }
    wht64_vec(a, b, lane);
    #pragma unroll
    for (int i = 0; i < 8; i++) {
        t[grp][sub * 8 + i]      = a[i];
        t[grp + 32][sub * 8 + i] = b[i];
    }
    __syncthreads();

    #pragma unroll
    for (int i = 0; i < 8; i++) {
        a[i] = t[sub * 8 + i][grp];
        b[i] = t[sub * 8 + i][grp + 32];
    }
    wht64_vec(a, b, lane);
    __syncthreads();
    #pragma unroll
    for (int i = 0; i < 8; i++) {
        t[sub * 8 + i][grp]      = a[i];
        t[sub * 8 + i][grp + 32] = b[i];
    }
    __syncthreads();

    const float inv = 1.0f / 4096.0f;
    #pragma unroll
    for (int i = 0; i < 16; i++) {
        int idx = tid + i * 256;
        out[base + idx] = fmaf(t[idx >> 6][idx & 63], inv, x[base + idx]);
    }
}

// ---------------------------------------------------------------------------
extern "C" void kernel_launch(void* const* d_in, const int* in_sizes, int n_in,
                              void* d_out, int out_size) {
    const float* x = (const float*)d_in[0];
    const float* v = (const float*)d_in[1];
    const float* W = (const float*)d_in[2];
    const float* T = (const float*)d_in[3];
    float* out = (float*)d_out;

    cudaFuncSetAttribute(k_gemm_fused,
                         cudaFuncAttributeMaxDynamicSharedMemorySize,
                         GEMM_SMEM_BYTES);

    k_pack_w<<<(2 * 32 * 16 * 32 + 255) / 256, 256>>>(W);
    k_fwht_fwd<<<NIMG, 256>>>(x);
    dim3 grid(HW / 64, CH / 128, BATCH);
    k_gemm_fused<<<grid, 256, GEMM_SMEM_BYTES>>>(v, T);
    k_fwht_inv<<<NIMG, 256>>>(x, out);
}

// round 10
// speedup vs baseline: 1.8582x; 1.0021x over previous
#include <cuda_runtime.h>
#include <cstdint>

// ---------------------------------------------------------------------------
// x: (32, 256, 64, 64) f32   v: (2, 64, 64)   W: (2, 256, 256)   T: (2, 64, 64)
// out = invWHT( sum_p soft( v_p * (W_p @ WHT(x)), T_p ) ) / 4096 + x
// ---------------------------------------------------------------------------

#define BATCH 32
#define CH    256
#define HW    4096
#define NIMG  (BATCH * CH)

__device__ float g_f2[(size_t)BATCH * CH * HW];   // WHT(x), tf32-rounded
__device__ float g_f6[(size_t)BATCH * CH * HW];   // pod-summed soft-thresholded
// W in tf32, pre-swizzled into mma fragment order:
//   [pod(2)][kq8(32)][mt16(16)][lane(32)][4 floats]
__device__ float g_WtF[2 * 32 * 16 * 32 * 4];

__device__ __forceinline__ float tf32_round(float v) {
    uint32_t u;
    asm("cvt.rna.tf32.f32 %0, %1;" : "=r"(u) : "f"(v));
    return __uint_as_float(u);
}

__device__ __forceinline__ float softthr(float s, float t) {
    float m = fmaxf(fabsf(s) - t, 0.0f);
    return copysignf(m, s);
}

// ---------------------------------------------------------------------------
// 64-pt WHT, data held as 8 CONSECUTIVE elements per thread (a[0..7] = elems
// 8*sub .. 8*sub+7, sub = lane & 7). Stages 1,2,4 are register-local;
// stages 8,16,32 are shfl.xor with masks 1,2,4 (within the 8-lane sub-group).
// ---------------------------------------------------------------------------
__device__ __forceinline__ void wht8_local(float (&a)[8]) {
    #pragma unroll
    for (int j = 0; j < 8; j += 2) { float s = a[j] + a[j+1], d = a[j] - a[j+1]; a[j] = s; a[j+1] = d; }
    #pragma unroll
    for (int j0 = 0; j0 < 8; j0 += 4)
        #pragma unroll
        for (int j = j0; j < j0 + 2; j++) { float s = a[j] + a[j+2], d = a[j] - a[j+2]; a[j] = s; a[j+2] = d; }
    #pragma unroll
    for (int j = 0; j < 4; j++) { float s = a[j] + a[j+4], d = a[j] - a[j+4]; a[j] = s; a[j+4] = d; }
}

__device__ __forceinline__ void wht64_vec(float (&a)[8], float (&b)[8], int lane) {
    wht8_local(a);
    wht8_local(b);
    #pragma unroll
    for (int mask = 1; mask <= 4; mask <<= 1) {
        bool hi = (lane & mask) != 0;
        #pragma unroll
        for (int i = 0; i < 8; i++) {
            float pa = __shfl_xor_sync(0xffffffffu, a[i], mask);
            float pb = __shfl_xor_sync(0xffffffffu, b[i], mask);
            a[i] = hi ? pa - a[i] : a[i] + pa;
            b[i] = hi ? pb - b[i] : b[i] + pb;
        }
    }
}

// ---------------------------------------------------------------------------
// Kernel 0: tf32-round W and scatter into mma fragment order.
// a0=W[m16+g][q8+t]  a1=W[m16+8+g][q8+t]  a2=W[m16+g][q8+t+4]  a3=W[..+8..][t+4]
// ---------------------------------------------------------------------------
__global__ void k_pack_w(const float* __restrict__ W) {
    int idx = blockIdx.x * blockDim.x + threadIdx.x;     // 32768 threads
    if (idx >= 2 * 32 * 16 * 32) return;
    int lane = idx & 31;
    int m    = (idx >> 5) & 15;
    int q    = (idx >> 9) & 31;
    int p    = idx >> 14;
    int g = lane >> 2, t = lane & 3;
    const float* Wp = W + p * 65536;
    float4 f;
    f.x = tf32_round(Wp[(m * 16 +     g) * 256 + q * 8 + t    ]);
    f.y = tf32_round(Wp[(m * 16 + 8 + g) * 256 + q * 8 + t    ]);
    f.z = tf32_round(Wp[(m * 16 +     g) * 256 + q * 8 + t + 4]);
    f.w = tf32_round(Wp[(m * 16 + 8 + g) * 256 + q * 8 + t + 4]);
    *reinterpret_cast<float4*>(&g_WtF[(size_t)idx * 4]) = f;
}

// ---------------------------------------------------------------------------
// Kernel 1: forward 2D FWHT (x -> g_f2, tf32-rounded)
// ---------------------------------------------------------------------------
__global__ __launch_bounds__(256) void k_fwht_fwd(const float* __restrict__ x) {
    __shared__ float t[64][65];
    const size_t base = (size_t)blockIdx.x * HW;
    const int tid = threadIdx.x, lane = tid & 31;
    const int sub = tid & 7;        // 8-elem chunk within the 64-vector
    const int grp = tid >> 3;       // 0..31
    float a[8], b[8];

    // row pass: rows grp and grp+32, cols 8*sub..8*sub+7
    {
        const float* r0 = &x[base + grp * 64 + sub * 8];
        const float* r1 = &x[base + (grp + 32) * 64 + sub * 8];
        *reinterpret_cast<float4*>(&a[0]) = *reinterpret_cast<const float4*>(r0);
        *reinterpret_cast<float4*>(&a[4]) = *reinterpret_cast<const float4*>(r0 + 4);
        *reinterpret_cast<float4*>(&b[0]) = *reinterpret_cast<const float4*>(r1);
        *reinterpret_cast<float4*>(&b[4]) = *reinterpret_cast<const float4*>(r1 + 4);
    }
    wht64_vec(a, b, lane);
    #pragma unroll
    for (int i = 0; i < 8; i++) {
        t[grp][sub * 8 + i]      = a[i];
        t[grp + 32][sub * 8 + i] = b[i];
    }
    __syncthreads();

    // column pass: cols grp and grp+32, rows 8*sub..8*sub+7
    #pragma unroll
    for (int i = 0; i < 8; i++) {
        a[i] = t[sub * 8 + i][grp];
        b[i] = t[sub * 8 + i][grp + 32];
    }
    wht64_vec(a, b, lane);
    __syncthreads();
    #pragma unroll
    for (int i = 0; i < 8; i++) {
        t[sub * 8 + i][grp]      = a[i];
        t[sub * 8 + i][grp + 32] = b[i];
    }
    __syncthreads();

    #pragma unroll
    for (int i = 0; i < 16; i++) {
        int idx = tid + i * 256;
        g_f2[base + idx] = tf32_round(t[idx >> 6][idx & 63]);
    }
}

// ---------------------------------------------------------------------------
// Kernel 2: fused dual-pod GEMM + v-scale + soft-threshold + pod-sum.
// BM=128 x BN=64, K=256 in 16-chunks, 3-stage cp.async, 1 sync/chunk.
// A consumed via LDS.128 from fragment-order smem; B XOR-swizzled.
// ---------------------------------------------------------------------------
#define A_STG 4096                        // floats per stage (2*2*8*32*4)
#define B_STG 1024                        // floats per stage (16*64)
#define STG   (A_STG + B_STG)             // 5120 floats
#define NSTAGE 3
#define GEMM_SMEM_BYTES (NSTAGE * STG * 4)   // 61440

__device__ __forceinline__ void cp_async16(void* smem, const void* gmem) {
    uint32_t s = (uint32_t)__cvta_generic_to_shared(smem);
    asm volatile("cp.async.ca.shared.global [%0], [%1], 16;\n" :: "r"(s), "l"(gmem));
}

__device__ __forceinline__ void mma_tf32(float& d0, float& d1, float& d2, float& d3,
                                         uint32_t a0, uint32_t a1, uint32_t a2, uint32_t a3,
                                         uint32_t b0, uint32_t b1) {
    asm volatile(
        "mma.sync.aligned.m16n8k8.row.col.f32.tf32.tf32.f32 "
        "{%0,%1,%2,%3}, {%4,%5,%6,%7}, {%8,%9}, {%0,%1,%2,%3};\n"
        : "+f"(d0), "+f"(d1), "+f"(d2), "+f"(d3)
        : "r"(a0), "r"(a1), "r"(a2), "r"(a3), "r"(b0), "r"(b1));
}

__global__ __launch_bounds__(256) void k_gemm_fused(const float* __restrict__ v,
                                                    const float* __restrict__ T) {
    extern __shared__ float smem[];

    const int tid  = threadIdx.x;
    const int warp = tid >> 5;
    const int lane = tid & 31;
    const int g = lane >> 2;
    const int t = lane & 3;
    const int warp_m = warp & 3;
    const int warp_n = warp >> 2;

    const int n0 = blockIdx.x * 64;
    const int m0 = blockIdx.y * 128;
    const int m16base = blockIdx.y * 8;
    const int b  = blockIdx.z;

    const float* f2b = g_f2 + (size_t)b * CH * HW;

    auto prefetch = [&](int kc, int st) {
        // A: 1024 16B-units in fragment-linear order
        #pragma unroll
        for (int i = 0; i < 4; i++) {
            int u  = i * 256 + tid;
            int p  = u >> 9;
            int r  = u & 511;
            int qq = r >> 8;
            int r2 = r & 255;
            int mm = r2 >> 5;
            int ln = r2 & 31;
            const float* src = &g_WtF[(size_t)((((p * 32 + kc * 2 + qq) * 16) + m16base + mm) * 32 + ln) * 4];
            cp_async16(&smem[st * STG + u * 4], src);
        }
        // B: 16 rows x 64 cols, XOR swizzle col ^= (k&3)<<3 (16B-chunk safe)
        {
            int kk = tid >> 4, c4 = (tid & 15) * 4;
            int col = c4 ^ ((kk & 3) << 3);
            cp_async16(&smem[st * STG + A_STG + kk * 64 + col],
                       &f2b[(size_t)(kc * 16 + kk) * HW + n0 + c4]);
        }
        asm volatile("cp.async.commit_group;\n");
    };

    float acc[2][2][4][4];
    #pragma unroll
    for (int p = 0; p < 2; p++)
        #pragma unroll
        for (int mt = 0; mt < 2; mt++)
            #pragma unroll
            for (int nt = 0; nt < 4; nt++)
                #pragma unroll
                for (int r = 0; r < 4; r++) acc[p][mt][nt][r] = 0.0f;

    prefetch(0, 0);
    prefetch(1, 1);

    for (int kc = 0; kc < 16; kc++) {
        const int st = kc % NSTAGE;
        __syncthreads();                         // all warps done with kc-1's buffer
        if (kc + 2 < 16) prefetch(kc + 2, (kc + 2) % NSTAGE);
        else asm volatile("cp.async.commit_group;\n");
        asm volatile("cp.async.wait_group 2;\n"); // stage kc resident
        __syncthreads();

        const float* sA = &smem[st * STG];
        const float* sB = &smem[st * STG + A_STG];

        #pragma unroll
        for (int kq = 0; kq < 2; kq++) {
            const int k8 = kq * 8;
            // B fragments (conflict-free: bank = g + 8*(nt^t))
            uint32_t bf[4][2];
            #pragma unroll
            for (int nt = 0; nt < 4; nt++) {
                int col = (warp_n * 32 + nt * 8 + g) ^ (t << 3);
                bf[nt][0] = __float_as_uint(sB[(k8 + t) * 64 + col]);
                bf[nt][1] = __float_as_uint(sB[(k8 + t + 4) * 64 + col]);
            }
            #pragma unroll
            for (int p = 0; p < 2; p++) {
                #pragma unroll
                for (int mt = 0; mt < 2; mt++) {
                    int u = p * 512 + kq * 256 + (warp_m * 2 + mt) * 32 + lane;
                    float4 af = *reinterpret_cast<const float4*>(&sA[u * 4]);
                    uint32_t a0 = __float_as_uint(af.x);
                    uint32_t a1 = __float_as_uint(af.y);
                    uint32_t a2 = __float_as_uint(af.z);
                    uint32_t a3 = __float_as_uint(af.w);
                    #pragma unroll
                    for (int nt = 0; nt < 4; nt++)
                        mma_tf32(acc[p][mt][nt][0], acc[p][mt][nt][1],
                                 acc[p][mt][nt][2], acc[p][mt][nt][3],
                                 a0, a1, a2, a3, bf[nt][0], bf[nt][1]);
                }
            }
        }
    }

    // Epilogue: v-scale, soft-threshold, sum pods
    float* f6b = g_f6 + (size_t)b * CH * HW;
    #pragma unroll
    for (int nt = 0; nt < 4; nt++) {
        int hw = n0 + warp_n * 32 + nt * 8 + 2 * t;
        float v0[2], v1[2], t0[2], t1[2];
        #pragma unroll
        for (int p = 0; p < 2; p++) {
            v0[p] = v[p * HW + hw];
            v1[p] = v[p * HW + hw + 1];
            t0[p] = T[p * HW + hw];
            t1[p] = T[p * HW + hw + 1];
        }
        #pragma unroll
        for (int mt = 0; mt < 2; mt++) {
            int o0 = m0 + warp_m * 32 + mt * 16 + g;
            float2 lo = make_float2(0.f, 0.f);
            float2 hi = make_float2(0.f, 0.f);
            #pragma unroll
            for (int p = 0; p < 2; p++) {
                lo.x += softthr(v0[p] * acc[p][mt][nt][0], t0[p]);
                lo.y += softthr(v1[p] * acc[p][mt][nt][1], t1[p]);
                hi.x += softthr(v0[p] * acc[p][mt][nt][2], t0[p]);
                hi.y += softthr(v1[p] * acc[p][mt][nt][3], t1[p]);
            }
            *reinterpret_cast<float2*>(&f6b[(size_t)o0 * HW + hw]) = lo;
            *reinterpret_cast<float2*>(&f6b[(size_t)(o0 + 8) * HW + hw]) = hi;
        }
    }
}

// ---------------------------------------------------------------------------
// Kernel 3: inverse 2D FWHT (*1/4096) + residual
// ---------------------------------------------------------------------------
__global__ __launch_bounds__(256) void k_fwht_inv(const float* __restrict__ x,
                                                  float* __restrict__ out) {
    __shared__ float t[64][65];
    const size_t base = (size_t)blockIdx.x * HW;
    const int tid = threadIdx.x, lane = tid & 31;
    const int sub = tid & 7;
    const int grp = tid >> 3;
    float a[8], b[8];

    {
        const float* r0 = &g_f6[base + grp * 64 + sub * 8];
        const float* r1 = &g_f6[base + (grp + 32) * 64 + sub * 8];
        *reinterpret_cast<float4*>(&a[0]) = *reinterpret_cast<const float4*>(r0);
        *reinterpret_cast<float4*>(&a[4]) = *reinterpret_cast<const float4*>(r0 + 4);
        *reinterpret_cast<float4*>(&b[0]) = *reinterpret_cast<const float4*>(r1);
        *reinterpret_cast<float4*>(&b[4]) = *reinterpret_cast<const float4*>(r1 + 4);
    }
    wht64_vec(a, b, lane);
    #pragma unroll
    for (int i = 0; i < 8; i++) {
        t[grp][sub * 8 + i]      = a[i];
        t[grp + 32][sub * 8 + i] = b[i];
    }
    __syncthreads();

    #pragma unroll
    for (int i = 0; i < 8; i++) {
        a[i] = t[sub * 8 + i][grp];
        b[i] = t[sub * 8 + i][grp + 32];
    }
    wht64_vec(a, b, lane);
    __syncthreads();
    #pragma unroll
    for (int i = 0; i < 8; i++) {
        t[sub * 8 + i][grp]      = a[i];
        t[sub * 8 + i][grp + 32] = b[i];
    }
    __syncthreads();

    const float inv = 1.0f / 4096.0f;
    #pragma unroll
    for (int i = 0; i < 16; i++) {
        int idx = tid + i * 256;
        out[base + idx] = fmaf(t[idx >> 6][idx & 63], inv, x[base + idx]);
    }
}

// ---------------------------------------------------------------------------
extern "C" void kernel_launch(void* const* d_in, const int* in_sizes, int n_in,
                              void* d_out, int out_size) {
    const float* x = (const float*)d_in[0];
    const float* v = (const float*)d_in[1];
    const float* W = (const float*)d_in[2];
    const float* T = (const float*)d_in[3];
    float* out = (float*)d_out;

    cudaFuncSetAttribute(k_gemm_fused,
                         cudaFuncAttributeMaxDynamicSharedMemorySize,
                         GEMM_SMEM_BYTES);

    k_pack_w<<<(2 * 32 * 16 * 32 + 255) / 256, 256>>>(W);
    k_fwht_fwd<<<NIMG, 256>>>(x);
    dim3 grid(HW / 64, CH / 128, BATCH);
    k_gemm_fused<<<grid, 256, GEMM_SMEM_BYTES>>>(v, T);
    k_fwht_inv<<<NIMG, 256>>>(x, out);
}

// round 11
// speedup vs baseline: 1.8603x; 1.0011x over previous
#include <cuda_runtime.h>
#include <cstdint>

// ---------------------------------------------------------------------------
// x: (32, 256, 64, 64) f32   v: (2, 64, 64)   W: (2, 256, 256)   T: (2, 64, 64)
// out = invWHT( sum_p soft( v_p * (W_p @ WHT(x)), T_p ) ) / 4096 + x
// ---------------------------------------------------------------------------

#define BATCH 32
#define CH    256
#define HW    4096
#define NIMG  (BATCH * CH)

__device__ float g_f2[(size_t)BATCH * CH * HW];   // WHT(x), tf32-rounded
__device__ float g_f6[(size_t)BATCH * CH * HW];   // pod-summed soft-thresholded
// W in tf32, pre-swizzled into mma fragment order:
//   [pod(2)][kq8(32)][mt16(16)][lane(32)][4 floats]
__device__ float g_WtF[2 * 32 * 16 * 32 * 4];

__device__ __forceinline__ float tf32_round(float v) {
    uint32_t u;
    asm("cvt.rna.tf32.f32 %0, %1;" : "=r"(u) : "f"(v));
    return __uint_as_float(u);
}

__device__ __forceinline__ float softthr(float s, float t) {
    float m = fmaxf(fabsf(s) - t, 0.0f);
    return copysignf(m, s);
}

// ---------------------------------------------------------------------------
// 64-pt WHT, data held as 8 CONSECUTIVE elements per thread (a[0..7] = elems
// 8*sub .. 8*sub+7, sub = lane & 7). Stages 1,2,4 are register-local;
// stages 8,16,32 are shfl.xor with masks 1,2,4 (within the 8-lane sub-group).
// ---------------------------------------------------------------------------
__device__ __forceinline__ void wht8_local(float (&a)[8]) {
    #pragma unroll
    for (int j = 0; j < 8; j += 2) { float s = a[j] + a[j+1], d = a[j] - a[j+1]; a[j] = s; a[j+1] = d; }
    #pragma unroll
    for (int j0 = 0; j0 < 8; j0 += 4)
        #pragma unroll
        for (int j = j0; j < j0 + 2; j++) { float s = a[j] + a[j+2], d = a[j] - a[j+2]; a[j] = s; a[j+2] = d; }
    #pragma unroll
    for (int j = 0; j < 4; j++) { float s = a[j] + a[j+4], d = a[j] - a[j+4]; a[j] = s; a[j+4] = d; }
}

__device__ __forceinline__ void wht64_vec(float (&a)[8], float (&b)[8], int lane) {
    wht8_local(a);
    wht8_local(b);
    #pragma unroll
    for (int mask = 1; mask <= 4; mask <<= 1) {
        bool hi = (lane & mask) != 0;
        #pragma unroll
        for (int i = 0; i < 8; i++) {
            float pa = __shfl_xor_sync(0xffffffffu, a[i], mask);
            float pb = __shfl_xor_sync(0xffffffffu, b[i], mask);
            a[i] = hi ? pa - a[i] : a[i] + pa;
            b[i] = hi ? pb - b[i] : b[i] + pb;
        }
    }
}

// ---------------------------------------------------------------------------
// Kernel 0: tf32-round W and scatter into mma fragment order.
// a0=W[m16+g][q8+t]  a1=W[m16+8+g][q8+t]  a2=W[m16+g][q8+t+4]  a3=W[..+8..][t+4]
// ---------------------------------------------------------------------------
__global__ void k_pack_w(const float* __restrict__ W) {
    int idx = blockIdx.x * blockDim.x + threadIdx.x;     // 32768 threads
    if (idx >= 2 * 32 * 16 * 32) return;
    int lane = idx & 31;
    int m    = (idx >> 5) & 15;
    int q    = (idx >> 9) & 31;
    int p    = idx >> 14;
    int g = lane >> 2, t = lane & 3;
    const float* Wp = W + p * 65536;
    float4 f;
    f.x = tf32_round(Wp[(m * 16 +     g) * 256 + q * 8 + t    ]);
    f.y = tf32_round(Wp[(m * 16 + 8 + g) * 256 + q * 8 + t    ]);
    f.z = tf32_round(Wp[(m * 16 +     g) * 256 + q * 8 + t + 4]);
    f.w = tf32_round(Wp[(m * 16 + 8 + g) * 256 + q * 8 + t + 4]);
    *reinterpret_cast<float4*>(&g_WtF[(size_t)idx * 4]) = f;
}

// ---------------------------------------------------------------------------
// Kernel 1: forward 2D FWHT (x -> g_f2, tf32-rounded)
// ---------------------------------------------------------------------------
__global__ __launch_bounds__(256) void k_fwht_fwd(const float* __restrict__ x) {
    __shared__ float t[64][65];
    const size_t base = (size_t)blockIdx.x * HW;
    const int tid = threadIdx.x, lane = tid & 31;
    const int sub = tid & 7;        // 8-elem chunk within the 64-vector
    const int grp = tid >> 3;       // 0..31
    float a[8], b[8];

    // row pass: rows grp and grp+32, cols 8*sub..8*sub+7
    {
        const float* r0 = &x[base + grp * 64 + sub * 8];
        const float* r1 = &x[base + (grp + 32) * 64 + sub * 8];
        *reinterpret_cast<float4*>(&a[0]) = *reinterpret_cast<const float4*>(r0);
        *reinterpret_cast<float4*>(&a[4]) = *reinterpret_cast<const float4*>(r0 + 4);
        *reinterpret_cast<float4*>(&b[0]) = *reinterpret_cast<const float4*>(r1);
        *reinterpret_cast<float4*>(&b[4]) = *reinterpret_cast<const float4*>(r1 + 4);
    }
    wht64_vec(a, b, lane);
    #pragma unroll
    for (int i = 0; i < 8; i++) {
        t[grp][sub * 8 + i]      = a[i];
        t[grp + 32][sub * 8 + i] = b[i];
    }
    __syncthreads();

    // column pass: cols grp and grp+32, rows 8*sub..8*sub+7
    #pragma unroll
    for (int i = 0; i < 8; i++) {
        a[i] = t[sub * 8 + i][grp];
        b[i] = t[sub * 8 + i][grp + 32];
    }
    wht64_vec(a, b, lane);
    __syncthreads();
    #pragma unroll
    for (int i = 0; i < 8; i++) {
        t[sub * 8 + i][grp]      = a[i];
        t[sub * 8 + i][grp + 32] = b[i];
    }
    __syncthreads();

    #pragma unroll
    for (int i = 0; i < 16; i++) {
        int idx = tid + i * 256;
        g_f2[base + idx] = tf32_round(t[idx >> 6][idx & 63]);
    }
}

// ---------------------------------------------------------------------------
// Kernel 2: fused dual-pod GEMM + v-scale + soft-threshold + pod-sum.
// BM=128 x BN=64, K=256 in 16-chunks, 3-stage cp.async, 1 sync/chunk.
// A consumed via LDS.128 from fragment-order smem; B XOR-swizzled.
// ---------------------------------------------------------------------------
#define A_STG 4096                        // floats per stage (2*2*8*32*4)
#define B_STG 1024                        // floats per stage (16*64)
#define STG   (A_STG + B_STG)             // 5120 floats
#define NSTAGE 3
#define GEMM_SMEM_BYTES (NSTAGE * STG * 4)   // 61440

__device__ __forceinline__ void cp_async16(void* smem, const void* gmem) {
    uint32_t s = (uint32_t)__cvta_generic_to_shared(smem);
    asm volatile("cp.async.ca.shared.global [%0], [%1], 16;\n" :: "r"(s), "l"(gmem));
}

__device__ __forceinline__ void mma_tf32(float& d0, float& d1, float& d2, float& d3,
                                         uint32_t a0, uint32_t a1, uint32_t a2, uint32_t a3,
                                         uint32_t b0, uint32_t b1) {
    asm volatile(
        "mma.sync.aligned.m16n8k8.row.col.f32.tf32.tf32.f32 "
        "{%0,%1,%2,%3}, {%4,%5,%6,%7}, {%8,%9}, {%0,%1,%2,%3};\n"
        : "+f"(d0), "+f"(d1), "+f"(d2), "+f"(d3)
        : "r"(a0), "r"(a1), "r"(a2), "r"(a3), "r"(b0), "r"(b1));
}

__global__ __launch_bounds__(256) void k_gemm_fused(const float* __restrict__ v,
                                                    const float* __restrict__ T) {
    extern __shared__ float smem[];

    const int tid  = threadIdx.x;
    const int warp = tid >> 5;
    const int lane = tid & 31;
    const int g = lane >> 2;
    const int t = lane & 3;
    const int warp_m = warp & 3;
    const int warp_n = warp >> 2;

    const int n0 = blockIdx.x * 64;
    const int m0 = blockIdx.y * 128;
    const int m16base = blockIdx.y * 8;
    const int b  = blockIdx.z;

    const float* f2b = g_f2 + (size_t)b * CH * HW;

    auto prefetch = [&](int kc, int st) {
        // A: 1024 16B-units in fragment-linear order
        #pragma unroll
        for (int i = 0; i < 4; i++) {
            int u  = i * 256 + tid;
            int p  = u >> 9;
            int r  = u & 511;
            int qq = r >> 8;
            int r2 = r & 255;
            int mm = r2 >> 5;
            int ln = r2 & 31;
            const float* src = &g_WtF[(size_t)((((p * 32 + kc * 2 + qq) * 16) + m16base + mm) * 32 + ln) * 4];
            cp_async16(&smem[st * STG + u * 4], src);
        }
        // B: 16 rows x 64 cols, XOR swizzle col ^= (k&3)<<3 (16B-chunk safe)
        {
            int kk = tid >> 4, c4 = (tid & 15) * 4;
            int col = c4 ^ ((kk & 3) << 3);
            cp_async16(&smem[st * STG + A_STG + kk * 64 + col],
                       &f2b[(size_t)(kc * 16 + kk) * HW + n0 + c4]);
        }
        asm volatile("cp.async.commit_group;\n");
    };

    float acc[2][2][4][4];
    #pragma unroll
    for (int p = 0; p < 2; p++)
        #pragma unroll
        for (int mt = 0; mt < 2; mt++)
            #pragma unroll
            for (int nt = 0; nt < 4; nt++)
                #pragma unroll
                for (int r = 0; r < 4; r++) acc[p][mt][nt][r] = 0.0f;

    prefetch(0, 0);
    prefetch(1, 1);

    for (int kc = 0; kc < 16; kc++) {
        const int st = kc % NSTAGE;
        __syncthreads();                         // all warps done with kc-1's buffer
        if (kc + 2 < 16) prefetch(kc + 2, (kc + 2) % NSTAGE);
        else asm volatile("cp.async.commit_group;\n");
        asm volatile("cp.async.wait_group 2;\n"); // stage kc resident
        __syncthreads();

        const float* sA = &smem[st * STG];
        const float* sB = &smem[st * STG + A_STG];

        #pragma unroll
        for (int kq = 0; kq < 2; kq++) {
            const int k8 = kq * 8;
            // B fragments (conflict-free: bank = g + 8*(nt^t))
            uint32_t bf[4][2];
            #pragma unroll
            for (int nt = 0; nt < 4; nt++) {
                int col = (warp_n * 32 + nt * 8 + g) ^ (t << 3);
                bf[nt][0] = __float_as_uint(sB[(k8 + t) * 64 + col]);
                bf[nt][1] = __float_as_uint(sB[(k8 + t + 4) * 64 + col]);
            }
            #pragma unroll
            for (int p = 0; p < 2; p++) {
                #pragma unroll
                for (int mt = 0; mt < 2; mt++) {
                    int u = p * 512 + kq * 256 + (warp_m * 2 + mt) * 32 + lane;
                    float4 af = *reinterpret_cast<const float4*>(&sA[u * 4]);
                    uint32_t a0 = __float_as_uint(af.x);
                    uint32_t a1 = __float_as_uint(af.y);
                    uint32_t a2 = __float_as_uint(af.z);
                    uint32_t a3 = __float_as_uint(af.w);
                    #pragma unroll
                    for (int nt = 0; nt < 4; nt++)
                        mma_tf32(acc[p][mt][nt][0], acc[p][mt][nt][1],
                                 acc[p][mt][nt][2], acc[p][mt][nt][3],
                                 a0, a1, a2, a3, bf[nt][0], bf[nt][1]);
                }
            }
        }
    }

    // Epilogue: v-scale, soft-threshold, sum pods
    float* f6b = g_f6 + (size_t)b * CH * HW;
    #pragma unroll
    for (int nt = 0; nt < 4; nt++) {
        int hw = n0 + warp_n * 32 + nt * 8 + 2 * t;
        float v0[2], v1[2], t0[2], t1[2];
        #pragma unroll
        for (int p = 0; p < 2; p++) {
            v0[p] = v[p * HW + hw];
            v1[p] = v[p * HW + hw + 1];
            t0[p] = T[p * HW + hw];
            t1[p] = T[p * HW + hw + 1];
        }
        #pragma unroll
        for (int mt = 0; mt < 2; mt++) {
            int o0 = m0 + warp_m * 32 + mt * 16 + g;
            float2 lo = make_float2(0.f, 0.f);
            float2 hi = make_float2(0.f, 0.f);
            #pragma unroll
            for (int p = 0; p < 2; p++) {
                lo.x += softthr(v0[p] * acc[p][mt][nt][0], t0[p]);
                lo.y += softthr(v1[p] * acc[p][mt][nt][1], t1[p]);
                hi.x += softthr(v0[p] * acc[p][mt][nt][2], t0[p]);
                hi.y += softthr(v1[p] * acc[p][mt][nt][3], t1[p]);
            }
            *reinterpret_cast<float2*>(&f6b[(size_t)o0 * HW + hw]) = lo;
            *reinterpret_cast<float2*>(&f6b[(size_t)(o0 + 8) * HW + hw]) = hi;
        }
    }
}

// ---------------------------------------------------------------------------
// Kernel 3: inverse 2D FWHT (*1/4096) + residual
// ---------------------------------------------------------------------------
__global__ __launch_bounds__(256) void k_fwht_inv(const float* __restrict__ x,
                                                  float* __restrict__ out) {
    __shared__ float t[64][65];
    const size_t base = (size_t)blockIdx.x * HW;
    const int tid = threadIdx.x, lane = tid & 31;
    const int sub = tid & 7;
    const int grp = tid >> 3;
    float a[8], b[8];

    {
        const float* r0 = &g_f6[base + grp * 64 + sub * 8];
        const float* r1 = &g_f6[base + (grp + 32) * 64 + sub * 8];
        *reinterpret_cast<float4*>(&a[0]) = *reinterpret_cast<const float4*>(r0);
        *reinterpret_cast<float4*>(&a[4]) = *reinterpret_cast<const float4*>(r0 + 4);
        *reinterpret_cast<float4*>(&b[0]) = *reinterpret_cast<const float4*>(r1);
        *reinterpret_cast<float4*>(&b[4]) = *reinterpret_cast<const float4*>(r1 + 4);
    }
    wht64_vec(a, b, lane);
    #pragma unroll
    for (int i = 0; i < 8; i++) {
        t[grp][sub * 8 + i]      = a[i];
        t[grp + 32][sub * 8 + i] = b[i];
    }
    __syncthreads();

    #pragma unroll
    for (int i = 0; i < 8; i++) {
        a[i] = t[sub * 8 + i][grp];
        b[i] = t[sub * 8 + i][grp + 32];
    }
    wht64_vec(a, b, lane);
    __syncthreads();
    #pragma unroll
    for (int i = 0; i < 8; i++) {
        t[sub * 8 + i][grp]      = a[i];
        t[sub * 8 + i][grp + 32] = b[i];
    }
    __syncthreads();

    const float inv = 1.0f / 4096.0f;
    #pragma unroll
    for (int i = 0; i < 16; i++) {
        int idx = tid + i * 256;
        out[base + idx] = fmaf(t[idx >> 6][idx & 63], inv, x[base + idx]);
    }
}

// ---------------------------------------------------------------------------
extern "C" void kernel_launch(void* const* d_in, const int* in_sizes, int n_in,
                              void* d_out, int out_size) {
    const float* x = (const float*)d_in[0];
    const float* v = (const float*)d_in[1];
    const float* W = (const float*)d_in[2];
    const float* T = (const float*)d_in[3];
    float* out = (float*)d_out;

    cudaFuncSetAttribute(k_gemm_fused,
                         cudaFuncAttributeMaxDynamicSharedMemorySize,
                         GEMM_SMEM_BYTES);

    k_pack_w<<<(2 * 32 * 16 * 32 + 255) / 256, 256>>>(W);
    k_fwht_fwd<<<NIMG, 256>>>(x);
    dim3 grid(HW / 64, CH / 128, BATCH);
    k_gemm_fused<<<grid, 256, GEMM_SMEM_BYTES>>>(v, T);
    k_fwht_inv<<<NIMG, 256>>>(x, out);
}